// round 15
// baseline (speedup 1.0000x reference)
#include <cuda_runtime.h>
#include <cuda_bf16.h>
#include <math.h>
#include <stdint.h>

#define B_SZ 256
#define S_SZ 512
#define V_SZ 50000
#define E_SZ 300
#define H_SZ 1024
#define KP   320

// persistent tiling: 4 mtiles(64) x 8 ntiles(128) x 4 kq(256) = 128 CTAs
// 4 CTAs of one tile (kq=0..3) = one cluster.
#define NCTA     128
#define MT       64
#define NTN      128
#define KQ       256
#define SW_BYTES   131072          // W: [2 term][8 ch][128 r][64B]
#define SH_BYTES   65536           // h: [2 buf][2 term][4 sub][64 r][64B]
#define STG_BYTES  32768           // DSMEM staging: 4 slots x 16r x 128c fp32
#define SMEM_RNN   (SW_BYTES + SH_BYTES + STG_BYTES)   // 229376

#define TB_STG   24576
#define SMEM_TAB (3 * TB_STG)

// ---------------- scratch ----------------
__device__ __align__(128) __nv_bfloat16 g_h_hi[2][B_SZ * H_SZ];
__device__ __align__(128) __nv_bfloat16 g_h_lo[2][B_SZ * H_SZ];
__device__ __align__(128) __nv_bfloat16 g_w_hi[H_SZ * H_SZ];
__device__ __align__(128) __nv_bfloat16 g_w_lo[H_SZ * H_SZ];
__device__ __align__(128) __nv_bfloat16 g_e_hi[(size_t)V_SZ * KP];
__device__ __align__(128) __nv_bfloat16 g_e_lo[(size_t)V_SZ * KP];
__device__ __align__(128) __nv_bfloat16 g_we_hi[H_SZ * KP];
__device__ __align__(128) __nv_bfloat16 g_we_lo[H_SZ * KP];
__device__ __align__(128) __nv_bfloat16 g_w1_hi[2 * H_SZ * H_SZ];
__device__ __align__(128) __nv_bfloat16 g_w1_lo[2 * H_SZ * H_SZ];
__device__ float g_table[(size_t)V_SZ * H_SZ];
__device__ float g_hid[B_SZ * 2 * H_SZ];
__device__ __align__(128) int g_done[32 * 32];   // 128B stride

// ---------------- PTX helpers ----------------
__device__ __forceinline__ uint32_t smem_u32(const void* p) {
    return (uint32_t)__cvta_generic_to_shared(p);
}
__device__ __forceinline__ void cp16(uint32_t dst, const void* src) {
    asm volatile("cp.async.cg.shared.global [%0], [%1], 16;" :: "r"(dst), "l"(src));
}
#define CP_COMMIT() asm volatile("cp.async.commit_group;" ::: "memory")
#define CP_WAIT_G2() asm volatile("cp.async.wait_group 2;" ::: "memory")
#define CP_WAIT_G1() asm volatile("cp.async.wait_group 1;" ::: "memory")
#define CP_WAIT_G0() asm volatile("cp.async.wait_group 0;" ::: "memory")
__device__ __forceinline__ void l2pf(const void* p) {
    asm volatile("prefetch.global.L2 [%0];" :: "l"(p));
}
__device__ __forceinline__ int ld_acq(const int* p) {
    int v;
    asm volatile("ld.acquire.gpu.global.b32 %0, [%1];" : "=r"(v) : "l"(p) : "memory");
    return v;
}
__device__ __forceinline__ void red_rel(int* p) {
    asm volatile("red.release.gpu.global.add.s32 [%0], 1;" :: "l"(p) : "memory");
}
__device__ __forceinline__ void ldmx4(uint32_t* r, uint32_t addr) {
    asm volatile("ldmatrix.sync.aligned.m8n8.x4.shared.b16 {%0,%1,%2,%3}, [%4];"
        : "=r"(r[0]), "=r"(r[1]), "=r"(r[2]), "=r"(r[3]) : "r"(addr));
}
__device__ __forceinline__ void mma16816(float* d, const uint32_t* a,
                                         const uint32_t b0, const uint32_t b1) {
    asm volatile("mma.sync.aligned.m16n8k16.row.col.f32.bf16.bf16.f32 "
        "{%0,%1,%2,%3}, {%4,%5,%6,%7}, {%8,%9}, {%0,%1,%2,%3};"
        : "+f"(d[0]), "+f"(d[1]), "+f"(d[2]), "+f"(d[3])
        : "r"(a[0]), "r"(a[1]), "r"(a[2]), "r"(a[3]), "r"(b0), "r"(b1));
}
__device__ __forceinline__ uint32_t mapa_u32(uint32_t addr, int rank) {
    uint32_t r;
    asm("mapa.shared::cluster.u32 %0, %1, %2;" : "=r"(r) : "r"(addr), "r"(rank));
    return r;
}
__device__ __forceinline__ void stc64(uint32_t addr, float a, float b) {
    uint64_t pk;
    asm("mov.b64 %0, {%1,%2};" : "=l"(pk) : "f"(a), "f"(b));
    asm volatile("st.shared::cluster.b64 [%0], %1;" :: "r"(addr), "l"(pk) : "memory");
}
#define CLUSTER_ARRIVE() asm volatile("barrier.cluster.arrive.aligned;" ::: "memory")
#define CLUSTER_WAIT()   asm volatile("barrier.cluster.wait.aligned;" ::: "memory")

// ---------------- persistent RNN kernel (512 threads, cluster-4) ----------------
__global__ void __launch_bounds__(512, 1) __cluster_dims__(4, 1, 1)
rnn_kernel(const int* __restrict__ x, const float* __restrict__ bias)
{
    extern __shared__ __align__(128) char smem[];
    const uint32_t sw = smem_u32(smem);
    const uint32_t sh = sw + SW_BYTES;
    const uint32_t sg = sh + SH_BYTES;                  // staging (local addr)
    float* stgp = reinterpret_cast<float*>(smem + SW_BYTES + SH_BYTES);

    const int tid  = threadIdx.x;
    const int lane = tid & 31;
    const int wid  = tid >> 5;
    const int wm   = wid >> 2;          // 0..3 (also: dest cluster rank)
    const int wn   = wid & 3;           // 0..3
    const int cta  = blockIdx.x;
    const int kq   = cta & 3;           // == cluster rank
    const int nidx = (cta >> 2) & 7;
    const int midx = cta >> 5;
    const int m0g  = midx * MT;
    const int n0g  = nidx * NTN;
    const int kbase = kq * KQ;
    const int tile  = midx * 8 + nidx;
    const int feedA = midx * 8 + 2 * kq;
    const int feedB = feedA + 1;

    // ---- W slice into smem (once) ----
    {
#pragma unroll
        for (int i = 0; i < 16; i++) {
            int u = tid + i * 512;
            int term = u >> 12;
            int v = u & 4095;
            int ch = v >> 9;
            int w2 = v & 511;
            int r = w2 >> 2, c = w2 & 3;
            const __nv_bfloat16* src = (term ? g_w_lo : g_w_hi)
                + (size_t)(n0g + r) * H_SZ + kbase + ch * 32 + c * 8;
            uint32_t dst = sw + term * 65536 + ch * 8192 + r * 64
                         + ((c ^ ((r >> 1) & 3)) << 4);
            cp16(dst, src);
        }
        CP_COMMIT(); CP_WAIT_G0();
        __syncthreads();
    }
    CLUSTER_ARRIVE();                    // matches the first read-done WAIT

    // ldmatrix lane geometry (warp tile 16M x 32N)
    const int rA = wm * 16 + (lane & 15);
    const int cAadd = lane >> 4;
    const int swzA = (rA >> 1) & 3;
    const int rowB0 = wn * 32 + ((lane >> 4) << 3) + (lane & 7);
    const int rowB1 = rowB0 + 16;
    const int cBadd = (lane >> 3) & 1;
    const int swzB = (rowB0 >> 1) & 3;

    // remote staging base for my strip (rank = wm), fixed all steps
    const uint32_t rbase = mapa_u32(sg, wm) + kq * 8192;

    // reduce-thread geometry + invariants
    const int rloc = tid >> 5;               // 0..15
    const int c0   = lane * 4;               // 0..124
    const int gr   = m0g + kq * 16 + rloc;
    const float4 bv = *reinterpret_cast<const float4*>(bias + n0g + c0);

    // issue one 32KB h half (128 K-cols): 2048 units, 4/thread
    auto issue_half = [&](const __nv_bfloat16* hhi_in,
                          const __nv_bfloat16* hlo_in, int buf) {
#pragma unroll
        for (int i = 0; i < 4; i++) {
            int v = tid + i * 512;
            int term = v >> 10;
            int w = v & 1023;
            int sub = w >> 8;
            int z = w & 255;
            int r = z >> 2, c = z & 3;
            const __nv_bfloat16* src = (term ? hlo_in : hhi_in)
                + (size_t)(m0g + r) * H_SZ + kbase + buf * 128 + sub * 32 + c * 8;
            uint32_t dst = sh + buf * 32768 + term * 16384 + sub * 4096
                         + r * 64 + ((c ^ ((r >> 1) & 3)) << 4);
            cp16(dst, src);
        }
        CP_COMMIT();
    };

    float acc[4][4];

    auto compute_half = [&](int buf) {
        const uint32_t hb = sh + buf * 32768;
#pragma unroll
        for (int kk2 = 0; kk2 < 8; kk2++) {
            const int sub = kk2 >> 1, kkin = kk2 & 1;
            const uint32_t hst = hb + sub * 4096;
            const uint32_t wst = sw + (buf * 4 + sub) * 8192;
            const int cA = ((kkin * 2 + cAadd) ^ swzA) << 4;
            const int cB = ((kkin * 2 + cBadd) ^ swzB) << 4;
            uint32_t ahi[4], alo[4], bhi[8], blo[8];
            ldmx4(ahi, hst + rA * 64 + cA);
            ldmx4(alo, hst + 16384 + rA * 64 + cA);
            ldmx4(bhi,     wst + rowB0 * 64 + cB);
            ldmx4(bhi + 4, wst + rowB1 * 64 + cB);
            ldmx4(blo,     wst + 65536 + rowB0 * 64 + cB);
            ldmx4(blo + 4, wst + 65536 + rowB1 * 64 + cB);
#pragma unroll
            for (int j = 0; j < 4; j++) {
                const uint32_t* b = &bhi[(j >> 1) * 4 + (j & 1) * 2];
                mma16816(acc[j], ahi, b[0], b[1]);
            }
#pragma unroll
            for (int j = 0; j < 4; j++) {
                const uint32_t* b = &blo[(j >> 1) * 4 + (j & 1) * 2];
                mma16816(acc[j], ahi, b[0], b[1]);
            }
#pragma unroll
            for (int j = 0; j < 4; j++) {
                const uint32_t* b = &bhi[(j >> 1) * 4 + (j & 1) * 2];
                mma16816(acc[j], alo, b[0], b[1]);
            }
        }
    };

    for (int t = 0; t < S_SZ; t++) {
        const __nv_bfloat16* hhi_in = g_h_hi[t & 1];
        const __nv_bfloat16* hlo_in = g_h_lo[t & 1];
        __nv_bfloat16* hhi_out = g_h_hi[(t + 1) & 1];
        __nv_bfloat16* hlo_out = g_h_lo[(t + 1) & 1];

        // table L2 prefetch FIRST — tokens independent of h, overlaps feed wait
        if (tid < 16) {
            int grp = m0g + kq * 16 + tid;
            int tok = x[(size_t)grp * S_SZ + t];
            const char* p = (const char*)(g_table + (size_t)tok * H_SZ + n0g);
            l2pf(p); l2pf(p + 128); l2pf(p + 256); l2pf(p + 384);
        }

        // ---- per-warp feed wait ----
        if (t > 0 && lane == 0) {
            const int tgt = 4 * t;
            while (ld_acq(&g_done[feedA * 32]) < tgt) __nanosleep(32);
            while (ld_acq(&g_done[feedB * 32]) < tgt) __nanosleep(32);
        }
        __syncwarp();

        issue_half(hhi_in, hlo_in, 0);
        issue_half(hhi_in, hlo_in, 1);

#pragma unroll
        for (int j = 0; j < 4; j++)
#pragma unroll
            for (int q = 0; q < 4; q++) acc[j][q] = 0.f;

        CP_WAIT_G1();
        __syncthreads();
        compute_half(0);
        CP_WAIT_G0();
        __syncthreads();
        compute_half(1);

        // ---- hoisted epilogue operands ----
        const int tok = x[(size_t)gr * S_SZ + t];
        const float4 tv = *reinterpret_cast<const float4*>(
            g_table + (size_t)tok * H_SZ + n0g + c0);

        // ---- DSMEM publish: warp's 16x128 strip -> reducer CTA rank wm,
        //      staging slot kq.  WAR protected by prior read-done barrier. ----
        CLUSTER_WAIT();                   // all cluster CTAs done reading t-1
        {
            const int lr = lane >> 2;     // 0..7
#pragma unroll
            for (int j = 0; j < 4; j++) {
                const int c = wn * 32 + j * 8 + 2 * (lane & 3);
                stc64(rbase + lr * 512 + c * 4,        acc[j][0], acc[j][1]);
                stc64(rbase + (lr + 8) * 512 + c * 4,  acc[j][2], acc[j][3]);
            }
        }
        CLUSTER_ARRIVE();                 // release my stores
        CLUSTER_WAIT();                   // acquire everyone's stores

        // ---- reduce my 16-row quarter + epilogue (all strips from SMEM) ----
        {
            const float* sp = stgp + rloc * 128 + c0;
            float4 s = make_float4(0.f, 0.f, 0.f, 0.f);
#pragma unroll
            for (int q = 0; q < 4; q++) {              // fixed order: deterministic
                float4 a = *reinterpret_cast<const float4*>(sp + q * 2048);
                s.x += a.x; s.y += a.y; s.z += a.z; s.w += a.w;
            }
            float v0 = tanhf(s.x + tv.x + bv.x);
            float v1 = tanhf(s.y + tv.y + bv.y);
            float v2 = tanhf(s.z + tv.z + bv.z);
            float v3 = tanhf(s.w + tv.w + bv.w);
            __nv_bfloat16 h4[4], l4[4];
            h4[0] = __float2bfloat16(v0); l4[0] = __float2bfloat16(v0 - __bfloat162float(h4[0]));
            h4[1] = __float2bfloat16(v1); l4[1] = __float2bfloat16(v1 - __bfloat162float(h4[1]));
            h4[2] = __float2bfloat16(v2); l4[2] = __float2bfloat16(v2 - __bfloat162float(h4[2]));
            h4[3] = __float2bfloat16(v3); l4[3] = __float2bfloat16(v3 - __bfloat162float(h4[3]));
            const size_t ob = (size_t)gr * H_SZ + n0g + c0;
            *reinterpret_cast<uint2*>(hhi_out + ob) = *reinterpret_cast<uint2*>(h4);
            *reinterpret_cast<uint2*>(hlo_out + ob) = *reinterpret_cast<uint2*>(l4);
        }
        CLUSTER_ARRIVE();                 // read-done(t): WAR guard for t+1
        __syncthreads();                  // all h writes before done-release
        if (tid == 0) red_rel(&g_done[tile * 32]);
    }
}

// ---------------- bf16-split GEMM (table precompute + MLP L1) ----------------
template<int MODE>
__global__ void __launch_bounds__(256) gemm_bf16s(
    const __nv_bfloat16* __restrict__ ahi_p, const __nv_bfloat16* __restrict__ alo_p,
    const __nv_bfloat16* __restrict__ bhi_p, const __nv_bfloat16* __restrict__ blo_p,
    int lda, int ldb, float* __restrict__ C, int ldc, int M, int NCH,
    const float* __restrict__ bias)
{
    extern __shared__ __align__(128) char smem[];
    const uint32_t sb = smem_u32(smem);
    const int tid  = threadIdx.x;
    const int lane = tid & 31;
    const int wid  = tid >> 5;
    const int wm   = wid >> 1;
    const int wn   = wid & 1;
    const int n0   = blockIdx.x * 64;
    const int m0   = blockIdx.y * 128;

    auto issue_tab = [&](uint32_t sbase, int ch) {
#pragma unroll
        for (int i = 0; i < 6; i++) {
            int u = tid + i * 256;
            if (u < 1024) {
                int term = u >> 9;
                int v = u & 511;
                int r = v >> 2, c = v & 3;
                int gm = m0 + r; if (gm >= M) gm = M - 1;
                const __nv_bfloat16* src = (term ? alo_p : ahi_p)
                    + (size_t)gm * lda + ch * 32 + c * 8;
                uint32_t dst = sbase + term * 8192 + r * 64
                             + ((c ^ ((r >> 1) & 3)) << 4);
                cp16(dst, src);
            } else {
                int v = u - 1024;
                int term = v >> 8;
                v &= 255;
                int r = v >> 2, c = v & 3;
                const __nv_bfloat16* src = (term ? blo_p : bhi_p)
                    + (size_t)(n0 + r) * ldb + ch * 32 + c * 8;
                uint32_t dst = sbase + 16384 + term * 4096 + r * 64
                             + ((c ^ ((r >> 1) & 3)) << 4);
                cp16(dst, src);
            }
        }
        CP_COMMIT();
    };

    issue_tab(sb + 0 * TB_STG, 0);
    issue_tab(sb + 1 * TB_STG, 1);
    issue_tab(sb + 2 * TB_STG, 2);

    const int rA0 = wm * 32 + (lane & 15);
    const int rA1 = rA0 + 16;
    const int cAadd = lane >> 4;
    const int swzA = (rA0 >> 1) & 3;
    const int rowB0 = wn * 32 + ((lane >> 4) << 3) + (lane & 7);
    const int rowB1 = rowB0 + 16;
    const int cBadd = (lane >> 3) & 1;
    const int swzB = (rowB0 >> 1) & 3;

    float acc[2][4][4];
#pragma unroll
    for (int i = 0; i < 2; i++)
#pragma unroll
        for (int j = 0; j < 4; j++)
#pragma unroll
            for (int q = 0; q < 4; q++) acc[i][j][q] = 0.f;

    for (int ch = 0; ch < NCH; ch++) {
        CP_WAIT_G2();
        __syncthreads();
        const uint32_t st = sb + (ch % 3) * TB_STG;
#pragma unroll
        for (int kk = 0; kk < 2; kk++) {
            const int cA = ((kk * 2 + cAadd) ^ swzA) << 4;
            const int cB = ((kk * 2 + cBadd) ^ swzB) << 4;
            uint32_t ahi[8], alo[8], bhi[8], blo[8];
            ldmx4(ahi,     st + rA0 * 64 + cA);
            ldmx4(ahi + 4, st + rA1 * 64 + cA);
            ldmx4(alo,     st + 8192 + rA0 * 64 + cA);
            ldmx4(alo + 4, st + 8192 + rA1 * 64 + cA);
            ldmx4(bhi,     st + 16384 + rowB0 * 64 + cB);
            ldmx4(bhi + 4, st + 16384 + rowB1 * 64 + cB);
            ldmx4(blo,     st + 20480 + rowB0 * 64 + cB);
            ldmx4(blo + 4, st + 20480 + rowB1 * 64 + cB);
#pragma unroll
            for (int i = 0; i < 2; i++)
#pragma unroll
                for (int j = 0; j < 4; j++) {
                    const uint32_t* b = &bhi[(j >> 1) * 4 + (j & 1) * 2];
                    mma16816(acc[i][j], ahi + i * 4, b[0], b[1]);
                }
#pragma unroll
            for (int i = 0; i < 2; i++)
#pragma unroll
                for (int j = 0; j < 4; j++) {
                    const uint32_t* b = &blo[(j >> 1) * 4 + (j & 1) * 2];
                    mma16816(acc[i][j], ahi + i * 4, b[0], b[1]);
                }
#pragma unroll
            for (int i = 0; i < 2; i++)
#pragma unroll
                for (int j = 0; j < 4; j++) {
                    const uint32_t* b = &bhi[(j >> 1) * 4 + (j & 1) * 2];
                    mma16816(acc[i][j], alo + i * 4, b[0], b[1]);
                }
        }
        __syncthreads();
        if (ch + 3 < NCH) issue_tab(sb + (ch % 3) * TB_STG, ch + 3);
        else CP_COMMIT();
    }

#pragma unroll
    for (int i = 0; i < 2; i++) {
        const int r = wm * 32 + i * 16 + (lane >> 2);
#pragma unroll
        for (int j = 0; j < 4; j++) {
            const int c = wn * 32 + j * 8 + 2 * (lane & 3);
            int gm = m0 + r;
            float2 v0 = make_float2(acc[i][j][0], acc[i][j][1]);
            float2 v1 = make_float2(acc[i][j][2], acc[i][j][3]);
            if (MODE == 1) {
                v0.x = fmaxf(v0.x + bias[n0 + c], 0.f);
                v0.y = fmaxf(v0.y + bias[n0 + c + 1], 0.f);
                v1.x = fmaxf(v1.x + bias[n0 + c], 0.f);
                v1.y = fmaxf(v1.y + bias[n0 + c + 1], 0.f);
            }
            if (gm < M)
                *reinterpret_cast<float2*>(C + (size_t)gm * ldc + n0 + c) = v0;
            if (gm + 8 < M)
                *reinterpret_cast<float2*>(C + (size_t)(gm + 8) * ldc + n0 + c) = v1;
        }
    }
}

// ---------------- prep / misc ----------------
__global__ void split_w_kernel(const float* __restrict__ W_ih,
                               __nv_bfloat16* __restrict__ whi,
                               __nv_bfloat16* __restrict__ wlo)
{
    int i = blockIdx.x * 256 + threadIdx.x;
    int j = i >> 10, k = i & (H_SZ - 1);
    float w = W_ih[(size_t)j * (E_SZ + H_SZ) + E_SZ + k];
    __nv_bfloat16 hi = __float2bfloat16(w);
    whi[i] = hi;
    wlo[i] = __float2bfloat16(w - __bfloat162float(hi));
}

__global__ void split_e_kernel(const float* __restrict__ embed_W)
{
    size_t id = (size_t)blockIdx.x * 256 + threadIdx.x;
    int row = (int)(id / KP);
    int col = (int)(id - (size_t)row * KP);
    float v = (col < E_SZ) ? embed_W[(size_t)row * E_SZ + col] : 0.f;
    __nv_bfloat16 hi = __float2bfloat16(v);
    g_e_hi[id] = hi;
    g_e_lo[id] = __float2bfloat16(v - __bfloat162float(hi));
}

__global__ void split_we_kernel(const float* __restrict__ W_ih)
{
    int id = blockIdx.x * 256 + threadIdx.x;
    int row = id / KP;
    int col = id - row * KP;
    float v = (col < E_SZ) ? W_ih[(size_t)row * (E_SZ + H_SZ) + col] : 0.f;
    __nv_bfloat16 hi = __float2bfloat16(v);
    g_we_hi[id] = hi;
    g_we_lo[id] = __float2bfloat16(v - __bfloat162float(hi));
}

__global__ void split_w1_kernel(const float* __restrict__ W1)
{
    int i = blockIdx.x * 256 + threadIdx.x;
    float w = W1[i];
    __nv_bfloat16 hi = __float2bfloat16(w);
    g_w1_hi[i] = hi;
    g_w1_lo[i] = __float2bfloat16(w - __bfloat162float(hi));
}

__global__ void init_kernel(__nv_bfloat16* hi, __nv_bfloat16* lo, int* done) {
    int i = blockIdx.x * 256 + threadIdx.x;
    hi[i] = __float2bfloat16(0.f);
    lo[i] = __float2bfloat16(0.f);
    if (i < 32 * 32) done[i] = 0;
}

__global__ void head2_kernel(const float* __restrict__ hid,
                             const float* __restrict__ W2,
                             const float* __restrict__ b2,
                             float* __restrict__ out)
{
    __shared__ float red[256];
    int b = blockIdx.x;
    float s = 0.f;
    for (int i = threadIdx.x; i < 2 * H_SZ; i += 256)
        s += hid[(size_t)b * 2 * H_SZ + i] * W2[i];
    red[threadIdx.x] = s;
    __syncthreads();
    for (int off = 128; off > 0; off >>= 1) {
        if (threadIdx.x < off) red[threadIdx.x] += red[threadIdx.x + off];
        __syncthreads();
    }
    if (threadIdx.x == 0) out[b] = red[0] + b2[0];
}

// ---------------- host ----------------
extern "C" void kernel_launch(void* const* d_in, const int* in_sizes, int n_in,
                              void* d_out, int out_size)
{
    const int*   x       = (const int*)  d_in[0];
    const float* embed_W = (const float*)d_in[1];
    const float* W_ih    = (const float*)d_in[2];
    const float* b_ih    = (const float*)d_in[3];
    const float* W1      = (const float*)d_in[4];
    const float* b1      = (const float*)d_in[5];
    const float* W2      = (const float*)d_in[6];
    const float* b2      = (const float*)d_in[7];
    float*       out     = (float*)d_out;

    float *table, *hid;
    int *done;
    __nv_bfloat16 *hhi0, *hlo0, *whi, *wlo, *ehi, *elo, *wehi, *welo, *w1hi, *w1lo;
    cudaGetSymbolAddress((void**)&table, g_table);
    cudaGetSymbolAddress((void**)&hid,   g_hid);
    cudaGetSymbolAddress((void**)&done,  g_done);
    {
        __nv_bfloat16* p;
        cudaGetSymbolAddress((void**)&p, g_h_hi);  hhi0 = p;
        cudaGetSymbolAddress((void**)&p, g_h_lo);  hlo0 = p;
        cudaGetSymbolAddress((void**)&p, g_w_hi);  whi = p;
        cudaGetSymbolAddress((void**)&p, g_w_lo);  wlo = p;
        cudaGetSymbolAddress((void**)&p, g_e_hi);  ehi = p;
        cudaGetSymbolAddress((void**)&p, g_e_lo);  elo = p;
        cudaGetSymbolAddress((void**)&p, g_we_hi); wehi = p;
        cudaGetSymbolAddress((void**)&p, g_we_lo); welo = p;
        cudaGetSymbolAddress((void**)&p, g_w1_hi); w1hi = p;
        cudaGetSymbolAddress((void**)&p, g_w1_lo); w1lo = p;
    }

    static bool attr_done = false;
    if (!attr_done) {
        cudaFuncSetAttribute(rnn_kernel,
            cudaFuncAttributeMaxDynamicSharedMemorySize, SMEM_RNN);
        cudaFuncSetAttribute(gemm_bf16s<0>,
            cudaFuncAttributeMaxDynamicSharedMemorySize, SMEM_TAB);
        cudaFuncSetAttribute(gemm_bf16s<1>,
            cudaFuncAttributeMaxDynamicSharedMemorySize, SMEM_TAB);
        attr_done = true;
    }

    init_kernel<<<(B_SZ * H_SZ) / 256, 256>>>(hhi0, hlo0, done);
    split_w_kernel<<<(H_SZ * H_SZ) / 256, 256>>>(W_ih, whi, wlo);
    split_e_kernel<<<(int)(((size_t)V_SZ * KP) / 256), 256>>>(embed_W);
    split_we_kernel<<<(H_SZ * KP) / 256, 256>>>(W_ih);
    split_w1_kernel<<<(2 * H_SZ * H_SZ) / 256, 256>>>(W1);

    // vocab table on tensor cores
    gemm_bf16s<0><<<dim3(H_SZ / 64, (V_SZ + 127) / 128), 256, SMEM_TAB>>>(
        ehi, elo, wehi, welo, KP, KP, table, H_SZ, V_SZ, KP / 32, nullptr);

    // all 512 recurrence steps in ONE persistent cluster kernel
    rnn_kernel<<<NCTA, 512, SMEM_RNN>>>(x, b_ih);

    // MLP L1 on tensor cores: hid = relu(h_last @ W1^T + b1)
    gemm_bf16s<1><<<dim3(2 * H_SZ / 64, B_SZ / 128), 256, SMEM_TAB>>>(
        hhi0, hlo0, w1hi, w1lo, H_SZ, H_SZ, hid, 2 * H_SZ, B_SZ, H_SZ / 32, b1);

    head2_kernel<<<B_SZ, 256>>>(hid, W2, b2, out);
}

// round 16
// speedup vs baseline: 1.0466x; 1.0466x over previous
#include <cuda_runtime.h>
#include <cuda_bf16.h>
#include <math.h>
#include <stdint.h>

#define B_SZ 256
#define S_SZ 512
#define V_SZ 50000
#define E_SZ 300
#define H_SZ 1024
#define KP   320

// persistent tiling: 4 mtiles(64) x 8 ntiles(128) x 4 kq(256) = 128 CTAs
#define NCTA     128
#define MT       64
#define NTN      128
#define KQ       256
#define SW_BYTES   131072          // W: [2 term][8 ch][128 r][64B]
#define SH_BYTES   65536           // h: [2 buf][2 term][4 sub][64 r][64B]
#define SMEM_RNN   (SW_BYTES + SH_BYTES)

#define TB_STG   24576
#define SMEM_TAB (3 * TB_STG)

// ---------------- scratch ----------------
__device__ __align__(128) __nv_bfloat16 g_h_hi[2][B_SZ * H_SZ];
__device__ __align__(128) __nv_bfloat16 g_h_lo[2][B_SZ * H_SZ];
__device__ __align__(128) __nv_bfloat16 g_w_hi[H_SZ * H_SZ];
__device__ __align__(128) __nv_bfloat16 g_w_lo[H_SZ * H_SZ];
__device__ __align__(128) __nv_bfloat16 g_e_hi[(size_t)V_SZ * KP];
__device__ __align__(128) __nv_bfloat16 g_e_lo[(size_t)V_SZ * KP];
__device__ __align__(128) __nv_bfloat16 g_we_hi[H_SZ * KP];
__device__ __align__(128) __nv_bfloat16 g_we_lo[H_SZ * KP];
__device__ __align__(128) __nv_bfloat16 g_w1_hi[2 * H_SZ * H_SZ];
__device__ __align__(128) __nv_bfloat16 g_w1_lo[2 * H_SZ * H_SZ];
__device__ float g_table[(size_t)V_SZ * H_SZ];
__device__ float g_hid[B_SZ * 2 * H_SZ];
__device__ __align__(128) float g_part[2][32 * 4 * MT * NTN];  // parity-doubled
__device__ __align__(128) int g_cnt[32 * 32];    // 128B stride
__device__ __align__(128) int g_done[32 * 32];   // 128B stride

// ---------------- PTX helpers ----------------
__device__ __forceinline__ uint32_t smem_u32(const void* p) {
    return (uint32_t)__cvta_generic_to_shared(p);
}
__device__ __forceinline__ void cp16(uint32_t dst, const void* src) {
    asm volatile("cp.async.cg.shared.global [%0], [%1], 16;" :: "r"(dst), "l"(src));
}
#define CP_COMMIT() asm volatile("cp.async.commit_group;" ::: "memory")
#define CP_WAIT_G3() asm volatile("cp.async.wait_group 3;" ::: "memory")
#define CP_WAIT_G2() asm volatile("cp.async.wait_group 2;" ::: "memory")
#define CP_WAIT_G1() asm volatile("cp.async.wait_group 1;" ::: "memory")
#define CP_WAIT_G0() asm volatile("cp.async.wait_group 0;" ::: "memory")
__device__ __forceinline__ void l2pf(const void* p) {
    asm volatile("prefetch.global.L2 [%0];" :: "l"(p));
}
__device__ __forceinline__ int ld_acq(const int* p) {
    int v;
    asm volatile("ld.acquire.gpu.global.b32 %0, [%1];" : "=r"(v) : "l"(p) : "memory");
    return v;
}
__device__ __forceinline__ void red_rel(int* p) {
    asm volatile("red.release.gpu.global.add.s32 [%0], 1;" :: "l"(p) : "memory");
}
__device__ __forceinline__ void ldmx4(uint32_t* r, uint32_t addr) {
    asm volatile("ldmatrix.sync.aligned.m8n8.x4.shared.b16 {%0,%1,%2,%3}, [%4];"
        : "=r"(r[0]), "=r"(r[1]), "=r"(r[2]), "=r"(r[3]) : "r"(addr));
}
__device__ __forceinline__ void mma16816(float* d, const uint32_t* a,
                                         const uint32_t b0, const uint32_t b1) {
    asm volatile("mma.sync.aligned.m16n8k16.row.col.f32.bf16.bf16.f32 "
        "{%0,%1,%2,%3}, {%4,%5,%6,%7}, {%8,%9}, {%0,%1,%2,%3};"
        : "+f"(d[0]), "+f"(d[1]), "+f"(d[2]), "+f"(d[3])
        : "r"(a[0]), "r"(a[1]), "r"(a[2]), "r"(a[3]), "r"(b0), "r"(b1));
}

// ---------------- persistent RNN kernel (512 threads) ----------------
__global__ void __launch_bounds__(512, 1) rnn_kernel(
    const int* __restrict__ x,
    const float* __restrict__ bias)
{
    extern __shared__ __align__(128) char smem[];
    const uint32_t sw = smem_u32(smem);
    const uint32_t sh = sw + SW_BYTES;
    float* stg = reinterpret_cast<float*>(smem + SW_BYTES);  // 16r x 128c staging

    const int tid  = threadIdx.x;
    const int lane = tid & 31;
    const int wid  = tid >> 5;
    const int wm   = wid >> 2;          // 0..3
    const int wn   = wid & 3;           // 0..3
    const int cta  = blockIdx.x;
    const int kq   = cta & 3;
    const int nidx = (cta >> 2) & 7;
    const int midx = cta >> 5;
    const int m0g  = midx * MT;
    const int n0g  = nidx * NTN;
    const int kbase = kq * KQ;
    const int tile  = midx * 8 + nidx;
    const int feedA = midx * 8 + 2 * kq;
    const int feedB = feedA + 1;

    // ---- W slice into smem (once) ----
    {
#pragma unroll
        for (int i = 0; i < 16; i++) {
            int u = tid + i * 512;
            int term = u >> 12;
            int v = u & 4095;
            int ch = v >> 9;
            int w2 = v & 511;
            int r = w2 >> 2, c = w2 & 3;
            const __nv_bfloat16* src = (term ? g_w_lo : g_w_hi)
                + (size_t)(n0g + r) * H_SZ + kbase + ch * 32 + c * 8;
            uint32_t dst = sw + term * 65536 + ch * 8192 + r * 64
                         + ((c ^ ((r >> 1) & 3)) << 4);
            cp16(dst, src);
        }
        CP_COMMIT(); CP_WAIT_G0();
        __syncthreads();
    }

    // ldmatrix lane geometry (warp tile 16M x 32N)
    const int rA = wm * 16 + (lane & 15);
    const int cAadd = lane >> 4;
    const int swzA = (rA >> 1) & 3;
    const int rowB0 = wn * 32 + ((lane >> 4) << 3) + (lane & 7);
    const int rowB1 = rowB0 + 16;
    const int cBadd = (lane >> 3) & 1;
    const int swzB = (rowB0 >> 1) & 3;

    // reduce-thread geometry + per-thread invariants hoisted out of the loop
    const int rloc = tid >> 5;               // 0..15
    const int c0   = lane * 4;               // 0..124
    const int pr   = kq * 16 + rloc;
    const int gr   = m0g + pr;
    const float4 bv = *reinterpret_cast<const float4*>(bias + n0g + c0);

    // issue one 16KB h quarter (64 K-cols): 1024 units, 2/thread
    auto issue_quarter = [&](const __nv_bfloat16* hhi_in,
                             const __nv_bfloat16* hlo_in, int q) {
#pragma unroll
        for (int i = 0; i < 2; i++) {
            int u = tid + i * 512;
            int term = u >> 9;
            int w = u & 511;
            int sin = w >> 8;                // 0..1 within quarter
            int z = w & 255;
            int r = z >> 2, c = z & 3;
            const __nv_bfloat16* src = (term ? hlo_in : hhi_in)
                + (size_t)(m0g + r) * H_SZ + kbase + q * 64 + sin * 32 + c * 8;
            uint32_t dst = sh + (q >> 1) * 32768 + term * 16384
                         + ((q & 1) * 2 + sin) * 4096
                         + r * 64 + ((c ^ ((r >> 1) & 3)) << 4);
            cp16(dst, src);
        }
        CP_COMMIT();
    };

    float acc[4][4];

    // compute one quarter q (64 K-cols): 4 kk2 x (4 LDSM + 12 MMA)
    auto compute_quarter = [&](int q) {
#pragma unroll
        for (int kk2 = 0; kk2 < 4; kk2++) {
            const int sin = kk2 >> 1, kkin = kk2 & 1;
            const uint32_t hst = sh + (q >> 1) * 32768
                               + ((q & 1) * 2 + sin) * 4096;
            const uint32_t wst = sw + (q * 2 + sin) * 8192;
            const int cA = ((kkin * 2 + cAadd) ^ swzA) << 4;
            const int cB = ((kkin * 2 + cBadd) ^ swzB) << 4;
            uint32_t ahi[4], alo[4], bhi[8], blo[8];
            ldmx4(ahi, hst + rA * 64 + cA);
            ldmx4(alo, hst + 16384 + rA * 64 + cA);
            ldmx4(bhi,     wst + rowB0 * 64 + cB);
            ldmx4(bhi + 4, wst + rowB1 * 64 + cB);
            ldmx4(blo,     wst + 65536 + rowB0 * 64 + cB);
            ldmx4(blo + 4, wst + 65536 + rowB1 * 64 + cB);
#pragma unroll
            for (int j = 0; j < 4; j++) {
                const uint32_t* b = &bhi[(j >> 1) * 4 + (j & 1) * 2];
                mma16816(acc[j], ahi, b[0], b[1]);
            }
#pragma unroll
            for (int j = 0; j < 4; j++) {
                const uint32_t* b = &blo[(j >> 1) * 4 + (j & 1) * 2];
                mma16816(acc[j], ahi, b[0], b[1]);
            }
#pragma unroll
            for (int j = 0; j < 4; j++) {
                const uint32_t* b = &bhi[(j >> 1) * 4 + (j & 1) * 2];
                mma16816(acc[j], alo, b[0], b[1]);
            }
        }
    };

    for (int t = 0; t < S_SZ; t++) {
        const __nv_bfloat16* hhi_in = g_h_hi[t & 1];
        const __nv_bfloat16* hlo_in = g_h_lo[t & 1];
        __nv_bfloat16* hhi_out = g_h_hi[(t + 1) & 1];
        __nv_bfloat16* hlo_out = g_h_lo[(t + 1) & 1];
        float* part = g_part[t & 1];

        // table L2 prefetch FIRST — tokens independent of h, overlaps feed wait
        if (tid < 16) {
            int grp = m0g + kq * 16 + tid;
            int tok = x[(size_t)grp * S_SZ + t];
            const char* p = (const char*)(g_table + (size_t)tok * H_SZ + n0g);
            l2pf(p); l2pf(p + 128); l2pf(p + 256); l2pf(p + 384);
        }

        // ---- per-warp feed wait ----
        if (t > 0 && lane == 0) {
            const int tgt = 4 * t;
            while (ld_acq(&g_done[feedA * 32]) < tgt) __nanosleep(32);
            while (ld_acq(&g_done[feedB * 32]) < tgt) __nanosleep(32);
        }
        __syncwarp();

        issue_quarter(hhi_in, hlo_in, 0);
        issue_quarter(hhi_in, hlo_in, 1);
        issue_quarter(hhi_in, hlo_in, 2);
        issue_quarter(hhi_in, hlo_in, 3);

#pragma unroll
        for (int j = 0; j < 4; j++)
#pragma unroll
            for (int q = 0; q < 4; q++) acc[j][q] = 0.f;

        CP_WAIT_G3(); __syncthreads(); compute_quarter(0);
        CP_WAIT_G2(); __syncthreads(); compute_quarter(1);
        CP_WAIT_G1(); __syncthreads(); compute_quarter(2);
        CP_WAIT_G0(); __syncthreads(); compute_quarter(3);

        // ---- hoisted epilogue operands: independent of partials ----
        const int tok = x[(size_t)gr * S_SZ + t];
        const float4 tv = *reinterpret_cast<const float4*>(
            g_table + (size_t)tok * H_SZ + n0g + c0);

        // ---- publish partials: own reduce strip (wm==kq) stays in SMEM,
        //      other strips go to the parity gmem buffer ----
        if (wm == kq) {
            const int lr = lane >> 2;                 // 0..7 within strip
#pragma unroll
            for (int j = 0; j < 4; j++) {
                const int c = wn * 32 + j * 8 + 2 * (lane & 3);
                *reinterpret_cast<float2*>(stg + lr * NTN + c) =
                    make_float2(acc[j][0], acc[j][1]);
                *reinterpret_cast<float2*>(stg + (lr + 8) * NTN + c) =
                    make_float2(acc[j][2], acc[j][3]);
            }
        } else {
            float* pb = part + ((size_t)tile * 4 + kq) * (MT * NTN);
            const int r = wm * 16 + (lane >> 2);
#pragma unroll
            for (int j = 0; j < 4; j++) {
                const int c = wn * 32 + j * 8 + 2 * (lane & 3);
                *reinterpret_cast<float2*>(pb + r * NTN + c) =
                    make_float2(acc[j][0], acc[j][1]);
                *reinterpret_cast<float2*>(pb + (r + 8) * NTN + c) =
                    make_float2(acc[j][2], acc[j][3]);
            }
        }
        __syncthreads();                  // publishes + stg visible block-wide
        if (tid == 0) red_rel(&g_cnt[tile * 32]);
        // ---- per-warp cnt wait ----
        if (lane == 0) {
            const int tgt = 4 * (t + 1);
            while (ld_acq(&g_cnt[tile * 32]) < tgt) __nanosleep(32);
        }
        __syncwarp();

        // ---- reduce my 16-row quarter + epilogue (own strip from SMEM) ----
        {
            const float* pb = part + (size_t)tile * 4 * (MT * NTN)
                            + pr * NTN + c0;
            float4 s = make_float4(0.f, 0.f, 0.f, 0.f);
#pragma unroll
            for (int q = 0; q < 4; q++) {              // fixed order: deterministic
                float4 a = (q == kq)
                    ? *reinterpret_cast<const float4*>(stg + rloc * NTN + c0)
                    : *reinterpret_cast<const float4*>(pb + q * (MT * NTN));
                s.x += a.x; s.y += a.y; s.z += a.z; s.w += a.w;
            }
            float v0 = tanhf(s.x + tv.x + bv.x);
            float v1 = tanhf(s.y + tv.y + bv.y);
            float v2 = tanhf(s.z + tv.z + bv.z);
            float v3 = tanhf(s.w + tv.w + bv.w);
            __nv_bfloat16 h4[4], l4[4];
            h4[0] = __float2bfloat16(v0); l4[0] = __float2bfloat16(v0 - __bfloat162float(h4[0]));
            h4[1] = __float2bfloat16(v1); l4[1] = __float2bfloat16(v1 - __bfloat162float(h4[1]));
            h4[2] = __float2bfloat16(v2); l4[2] = __float2bfloat16(v2 - __bfloat162float(h4[2]));
            h4[3] = __float2bfloat16(v3); l4[3] = __float2bfloat16(v3 - __bfloat162float(h4[3]));
            const size_t ob = (size_t)gr * H_SZ + n0g + c0;
            *reinterpret_cast<uint2*>(hhi_out + ob) = *reinterpret_cast<uint2*>(h4);
            *reinterpret_cast<uint2*>(hlo_out + ob) = *reinterpret_cast<uint2*>(l4);
        }
        __syncthreads();                  // all h writes done before done-release
        if (tid == 0) red_rel(&g_done[tile * 32]);
    }
}

// ---------------- bf16-split GEMM (table precompute + MLP L1) ----------------
// MODE 0: plain fp32 store   MODE 1: relu(acc + bias[n])
template<int MODE>
__global__ void __launch_bounds__(256) gemm_bf16s(
    const __nv_bfloat16* __restrict__ ahi_p, const __nv_bfloat16* __restrict__ alo_p,
    const __nv_bfloat16* __restrict__ bhi_p, const __nv_bfloat16* __restrict__ blo_p,
    int lda, int ldb, float* __restrict__ C, int ldc, int M, int NCH,
    const float* __restrict__ bias)
{
    extern __shared__ __align__(128) char smem[];
    const uint32_t sb = smem_u32(smem);
    const int tid  = threadIdx.x;
    const int lane = tid & 31;
    const int wid  = tid >> 5;
    const int wm   = wid >> 1;
    const int wn   = wid & 1;
    const int n0   = blockIdx.x * 64;
    const int m0   = blockIdx.y * 128;

    auto issue_tab = [&](uint32_t sbase, int ch) {
#pragma unroll
        for (int i = 0; i < 6; i++) {
            int u = tid + i * 256;
            if (u < 1024) {
                int term = u >> 9;
                int v = u & 511;
                int r = v >> 2, c = v & 3;
                int gm = m0 + r; if (gm >= M) gm = M - 1;
                const __nv_bfloat16* src = (term ? alo_p : ahi_p)
                    + (size_t)gm * lda + ch * 32 + c * 8;
                uint32_t dst = sbase + term * 8192 + r * 64
                             + ((c ^ ((r >> 1) & 3)) << 4);
                cp16(dst, src);
            } else {
                int v = u - 1024;
                int term = v >> 8;
                v &= 255;
                int r = v >> 2, c = v & 3;
                const __nv_bfloat16* src = (term ? blo_p : bhi_p)
                    + (size_t)(n0 + r) * ldb + ch * 32 + c * 8;
                uint32_t dst = sbase + 16384 + term * 4096 + r * 64
                             + ((c ^ ((r >> 1) & 3)) << 4);
                cp16(dst, src);
            }
        }
        CP_COMMIT();
    };

    issue_tab(sb + 0 * TB_STG, 0);
    issue_tab(sb + 1 * TB_STG, 1);
    issue_tab(sb + 2 * TB_STG, 2);

    const int rA0 = wm * 32 + (lane & 15);
    const int rA1 = rA0 + 16;
    const int cAadd = lane >> 4;
    const int swzA = (rA0 >> 1) & 3;
    const int rowB0 = wn * 32 + ((lane >> 4) << 3) + (lane & 7);
    const int rowB1 = rowB0 + 16;
    const int cBadd = (lane >> 3) & 1;
    const int swzB = (rowB0 >> 1) & 3;

    float acc[2][4][4];
#pragma unroll
    for (int i = 0; i < 2; i++)
#pragma unroll
        for (int j = 0; j < 4; j++)
#pragma unroll
            for (int q = 0; q < 4; q++) acc[i][j][q] = 0.f;

    for (int ch = 0; ch < NCH; ch++) {
        CP_WAIT_G2();
        __syncthreads();
        const uint32_t st = sb + (ch % 3) * TB_STG;
#pragma unroll
        for (int kk = 0; kk < 2; kk++) {
            const int cA = ((kk * 2 + cAadd) ^ swzA) << 4;
            const int cB = ((kk * 2 + cBadd) ^ swzB) << 4;
            uint32_t ahi[8], alo[8], bhi[8], blo[8];
            ldmx4(ahi,     st + rA0 * 64 + cA);
            ldmx4(ahi + 4, st + rA1 * 64 + cA);
            ldmx4(alo,     st + 8192 + rA0 * 64 + cA);
            ldmx4(alo + 4, st + 8192 + rA1 * 64 + cA);
            ldmx4(bhi,     st + 16384 + rowB0 * 64 + cB);
            ldmx4(bhi + 4, st + 16384 + rowB1 * 64 + cB);
            ldmx4(blo,     st + 20480 + rowB0 * 64 + cB);
            ldmx4(blo + 4, st + 20480 + rowB1 * 64 + cB);
#pragma unroll
            for (int i = 0; i < 2; i++)
#pragma unroll
                for (int j = 0; j < 4; j++) {
                    const uint32_t* b = &bhi[(j >> 1) * 4 + (j & 1) * 2];
                    mma16816(acc[i][j], ahi + i * 4, b[0], b[1]);
                }
#pragma unroll
            for (int i = 0; i < 2; i++)
#pragma unroll
                for (int j = 0; j < 4; j++) {
                    const uint32_t* b = &blo[(j >> 1) * 4 + (j & 1) * 2];
                    mma16816(acc[i][j], ahi + i * 4, b[0], b[1]);
                }
#pragma unroll
            for (int i = 0; i < 2; i++)
#pragma unroll
                for (int j = 0; j < 4; j++) {
                    const uint32_t* b = &bhi[(j >> 1) * 4 + (j & 1) * 2];
                    mma16816(acc[i][j], alo + i * 4, b[0], b[1]);
                }
        }
        __syncthreads();
        if (ch + 3 < NCH) issue_tab(sb + (ch % 3) * TB_STG, ch + 3);
        else CP_COMMIT();
    }

#pragma unroll
    for (int i = 0; i < 2; i++) {
        const int r = wm * 32 + i * 16 + (lane >> 2);
#pragma unroll
        for (int j = 0; j < 4; j++) {
            const int c = wn * 32 + j * 8 + 2 * (lane & 3);
            int gm = m0 + r;
            float2 v0 = make_float2(acc[i][j][0], acc[i][j][1]);
            float2 v1 = make_float2(acc[i][j][2], acc[i][j][3]);
            if (MODE == 1) {
                v0.x = fmaxf(v0.x + bias[n0 + c], 0.f);
                v0.y = fmaxf(v0.y + bias[n0 + c + 1], 0.f);
                v1.x = fmaxf(v1.x + bias[n0 + c], 0.f);
                v1.y = fmaxf(v1.y + bias[n0 + c + 1], 0.f);
            }
            if (gm < M)
                *reinterpret_cast<float2*>(C + (size_t)gm * ldc + n0 + c) = v0;
            if (gm + 8 < M)
                *reinterpret_cast<float2*>(C + (size_t)(gm + 8) * ldc + n0 + c) = v1;
        }
    }
}

// ---------------- prep / misc ----------------
__global__ void split_w_kernel(const float* __restrict__ W_ih,
                               __nv_bfloat16* __restrict__ whi,
                               __nv_bfloat16* __restrict__ wlo)
{
    int i = blockIdx.x * 256 + threadIdx.x;
    int j = i >> 10, k = i & (H_SZ - 1);
    float w = W_ih[(size_t)j * (E_SZ + H_SZ) + E_SZ + k];
    __nv_bfloat16 hi = __float2bfloat16(w);
    whi[i] = hi;
    wlo[i] = __float2bfloat16(w - __bfloat162float(hi));
}

__global__ void split_e_kernel(const float* __restrict__ embed_W)
{
    size_t id = (size_t)blockIdx.x * 256 + threadIdx.x;
    int row = (int)(id / KP);
    int col = (int)(id - (size_t)row * KP);
    float v = (col < E_SZ) ? embed_W[(size_t)row * E_SZ + col] : 0.f;
    __nv_bfloat16 hi = __float2bfloat16(v);
    g_e_hi[id] = hi;
    g_e_lo[id] = __float2bfloat16(v - __bfloat162float(hi));
}

__global__ void split_we_kernel(const float* __restrict__ W_ih)
{
    int id = blockIdx.x * 256 + threadIdx.x;
    int row = id / KP;
    int col = id - row * KP;
    float v = (col < E_SZ) ? W_ih[(size_t)row * (E_SZ + H_SZ) + col] : 0.f;
    __nv_bfloat16 hi = __float2bfloat16(v);
    g_we_hi[id] = hi;
    g_we_lo[id] = __float2bfloat16(v - __bfloat162float(hi));
}

__global__ void split_w1_kernel(const float* __restrict__ W1)
{
    int i = blockIdx.x * 256 + threadIdx.x;
    float w = W1[i];
    __nv_bfloat16 hi = __float2bfloat16(w);
    g_w1_hi[i] = hi;
    g_w1_lo[i] = __float2bfloat16(w - __bfloat162float(hi));
}

__global__ void init_kernel(__nv_bfloat16* hi, __nv_bfloat16* lo,
                            int* cnt, int* done) {
    int i = blockIdx.x * 256 + threadIdx.x;
    hi[i] = __float2bfloat16(0.f);
    lo[i] = __float2bfloat16(0.f);
    if (i < 32 * 32) { cnt[i] = 0; done[i] = 0; }
}

__global__ void head2_kernel(const float* __restrict__ hid,
                             const float* __restrict__ W2,
                             const float* __restrict__ b2,
                             float* __restrict__ out)
{
    __shared__ float red[256];
    int b = blockIdx.x;
    float s = 0.f;
    for (int i = threadIdx.x; i < 2 * H_SZ; i += 256)
        s += hid[(size_t)b * 2 * H_SZ + i] * W2[i];
    red[threadIdx.x] = s;
    __syncthreads();
    for (int off = 128; off > 0; off >>= 1) {
        if (threadIdx.x < off) red[threadIdx.x] += red[threadIdx.x + off];
        __syncthreads();
    }
    if (threadIdx.x == 0) out[b] = red[0] + b2[0];
}

// ---------------- host ----------------
extern "C" void kernel_launch(void* const* d_in, const int* in_sizes, int n_in,
                              void* d_out, int out_size)
{
    const int*   x       = (const int*)  d_in[0];
    const float* embed_W = (const float*)d_in[1];
    const float* W_ih    = (const float*)d_in[2];
    const float* b_ih    = (const float*)d_in[3];
    const float* W1      = (const float*)d_in[4];
    const float* b1      = (const float*)d_in[5];
    const float* W2      = (const float*)d_in[6];
    const float* b2      = (const float*)d_in[7];
    float*       out     = (float*)d_out;

    float *table, *hid;
    int *cnt, *done;
    __nv_bfloat16 *hhi0, *hlo0, *whi, *wlo, *ehi, *elo, *wehi, *welo, *w1hi, *w1lo;
    cudaGetSymbolAddress((void**)&table, g_table);
    cudaGetSymbolAddress((void**)&hid,   g_hid);
    cudaGetSymbolAddress((void**)&cnt,   g_cnt);
    cudaGetSymbolAddress((void**)&done,  g_done);
    {
        __nv_bfloat16* p;
        cudaGetSymbolAddress((void**)&p, g_h_hi);  hhi0 = p;
        cudaGetSymbolAddress((void**)&p, g_h_lo);  hlo0 = p;
        cudaGetSymbolAddress((void**)&p, g_w_hi);  whi = p;
        cudaGetSymbolAddress((void**)&p, g_w_lo);  wlo = p;
        cudaGetSymbolAddress((void**)&p, g_e_hi);  ehi = p;
        cudaGetSymbolAddress((void**)&p, g_e_lo);  elo = p;
        cudaGetSymbolAddress((void**)&p, g_we_hi); wehi = p;
        cudaGetSymbolAddress((void**)&p, g_we_lo); welo = p;
        cudaGetSymbolAddress((void**)&p, g_w1_hi); w1hi = p;
        cudaGetSymbolAddress((void**)&p, g_w1_lo); w1lo = p;
    }

    static bool attr_done = false;
    if (!attr_done) {
        cudaFuncSetAttribute(rnn_kernel,
            cudaFuncAttributeMaxDynamicSharedMemorySize, SMEM_RNN);
        cudaFuncSetAttribute(gemm_bf16s<0>,
            cudaFuncAttributeMaxDynamicSharedMemorySize, SMEM_TAB);
        cudaFuncSetAttribute(gemm_bf16s<1>,
            cudaFuncAttributeMaxDynamicSharedMemorySize, SMEM_TAB);
        attr_done = true;
    }

    init_kernel<<<(B_SZ * H_SZ) / 256, 256>>>(hhi0, hlo0, cnt, done);
    split_w_kernel<<<(H_SZ * H_SZ) / 256, 256>>>(W_ih, whi, wlo);
    split_e_kernel<<<(int)(((size_t)V_SZ * KP) / 256), 256>>>(embed_W);
    split_we_kernel<<<(H_SZ * KP) / 256, 256>>>(W_ih);
    split_w1_kernel<<<(2 * H_SZ * H_SZ) / 256, 256>>>(W1);

    // vocab table on tensor cores
    gemm_bf16s<0><<<dim3(H_SZ / 64, (V_SZ + 127) / 128), 256, SMEM_TAB>>>(
        ehi, elo, wehi, welo, KP, KP, table, H_SZ, V_SZ, KP / 32, nullptr);

    // all 512 recurrence steps in ONE persistent kernel
    rnn_kernel<<<NCTA, 512, SMEM_RNN>>>(x, b_ih);

    // MLP L1 on tensor cores: hid = relu(h_last @ W1^T + b1)
    gemm_bf16s<1><<<dim3(2 * H_SZ / 64, B_SZ / 128), 256, SMEM_TAB>>>(
        hhi0, hlo0, w1hi, w1lo, H_SZ, H_SZ, hid, 2 * H_SZ, B_SZ, H_SZ / 32, b1);

    head2_kernel<<<B_SZ, 256>>>(hid, W2, b2, out);
}

// round 17
// speedup vs baseline: 1.1643x; 1.1125x over previous
#include <cuda_runtime.h>
#include <cuda_bf16.h>
#include <cuda_fp16.h>
#include <math.h>
#include <stdint.h>

#define B_SZ 256
#define S_SZ 512
#define V_SZ 50000
#define E_SZ 300
#define H_SZ 1024
#define KP   320

// persistent tiling: 4 mtiles(64) x 8 ntiles(128) x 4 kq(256) = 128 CTAs
#define NCTA     128
#define MT       64
#define NTN      128
#define KQ       256
#define SW_BYTES   131072          // W fp16: [2 term][8 ch][128 r][64B]
#define SH_BYTES   32768           // h fp16 single: [4 q][2 sub][64 r][64B]
#define SMEM_RNN   (SW_BYTES + SH_BYTES)

#define TB_STG   24576
#define SMEM_TAB (3 * TB_STG)

// ---------------- scratch ----------------
__device__ __align__(128) __half g_h[2][B_SZ * H_SZ];          // fp16 hidden
__device__ __align__(128) __half g_w_hi[H_SZ * H_SZ];          // fp16 W split
__device__ __align__(128) __half g_w_lo[H_SZ * H_SZ];
__device__ __align__(128) __nv_bfloat16 g_hl_hi[B_SZ * H_SZ];  // h_last bf16 split
__device__ __align__(128) __nv_bfloat16 g_hl_lo[B_SZ * H_SZ];
__device__ __align__(128) __nv_bfloat16 g_e_hi[(size_t)V_SZ * KP];
__device__ __align__(128) __nv_bfloat16 g_e_lo[(size_t)V_SZ * KP];
__device__ __align__(128) __nv_bfloat16 g_we_hi[H_SZ * KP];
__device__ __align__(128) __nv_bfloat16 g_we_lo[H_SZ * KP];
__device__ __align__(128) __nv_bfloat16 g_w1_hi[2 * H_SZ * H_SZ];
__device__ __align__(128) __nv_bfloat16 g_w1_lo[2 * H_SZ * H_SZ];
__device__ float g_table[(size_t)V_SZ * H_SZ];
__device__ float g_hid[B_SZ * 2 * H_SZ];
__device__ __align__(128) float g_part[2][32 * 4 * MT * NTN];  // parity-doubled
__device__ __align__(128) int g_cnt[32 * 32];    // 128B stride
__device__ __align__(128) int g_done[32 * 32];   // 128B stride

// ---------------- PTX helpers ----------------
__device__ __forceinline__ uint32_t smem_u32(const void* p) {
    return (uint32_t)__cvta_generic_to_shared(p);
}
__device__ __forceinline__ void cp16(uint32_t dst, const void* src) {
    asm volatile("cp.async.cg.shared.global [%0], [%1], 16;" :: "r"(dst), "l"(src));
}
#define CP_COMMIT() asm volatile("cp.async.commit_group;" ::: "memory")
#define CP_WAIT_G3() asm volatile("cp.async.wait_group 3;" ::: "memory")
#define CP_WAIT_G2() asm volatile("cp.async.wait_group 2;" ::: "memory")
#define CP_WAIT_G1() asm volatile("cp.async.wait_group 1;" ::: "memory")
#define CP_WAIT_G0() asm volatile("cp.async.wait_group 0;" ::: "memory")
__device__ __forceinline__ void l2pf(const void* p) {
    asm volatile("prefetch.global.L2 [%0];" :: "l"(p));
}
__device__ __forceinline__ int ld_acq(const int* p) {
    int v;
    asm volatile("ld.acquire.gpu.global.b32 %0, [%1];" : "=r"(v) : "l"(p) : "memory");
    return v;
}
__device__ __forceinline__ void red_rel(int* p) {
    asm volatile("red.release.gpu.global.add.s32 [%0], 1;" :: "l"(p) : "memory");
}
__device__ __forceinline__ void ldmx4(uint32_t* r, uint32_t addr) {
    asm volatile("ldmatrix.sync.aligned.m8n8.x4.shared.b16 {%0,%1,%2,%3}, [%4];"
        : "=r"(r[0]), "=r"(r[1]), "=r"(r[2]), "=r"(r[3]) : "r"(addr));
}
__device__ __forceinline__ void mma16816bf(float* d, const uint32_t* a,
                                           const uint32_t b0, const uint32_t b1) {
    asm volatile("mma.sync.aligned.m16n8k16.row.col.f32.bf16.bf16.f32 "
        "{%0,%1,%2,%3}, {%4,%5,%6,%7}, {%8,%9}, {%0,%1,%2,%3};"
        : "+f"(d[0]), "+f"(d[1]), "+f"(d[2]), "+f"(d[3])
        : "r"(a[0]), "r"(a[1]), "r"(a[2]), "r"(a[3]), "r"(b0), "r"(b1));
}
__device__ __forceinline__ void mma16816h(float* d, const uint32_t* a,
                                          const uint32_t b0, const uint32_t b1) {
    asm volatile("mma.sync.aligned.m16n8k16.row.col.f32.f16.f16.f32 "
        "{%0,%1,%2,%3}, {%4,%5,%6,%7}, {%8,%9}, {%0,%1,%2,%3};"
        : "+f"(d[0]), "+f"(d[1]), "+f"(d[2]), "+f"(d[3])
        : "r"(a[0]), "r"(a[1]), "r"(a[2]), "r"(a[3]), "r"(b0), "r"(b1));
}

// ---------------- persistent RNN kernel (512 threads, fp16 math) ----------------
__global__ void __launch_bounds__(512, 1) rnn_kernel(
    const int* __restrict__ x,
    const float* __restrict__ bias)
{
    extern __shared__ __align__(128) char smem[];
    const uint32_t sw = smem_u32(smem);
    const uint32_t sh = sw + SW_BYTES;
    float* stg = reinterpret_cast<float*>(smem + SW_BYTES);  // 16r x 128c staging
                                                             // (overlaps h q0/q1)
    const int tid  = threadIdx.x;
    const int lane = tid & 31;
    const int wid  = tid >> 5;
    const int wm   = wid >> 2;          // 0..3
    const int wn   = wid & 3;           // 0..3
    const int cta  = blockIdx.x;
    const int kq   = cta & 3;
    const int nidx = (cta >> 2) & 7;
    const int midx = cta >> 5;
    const int m0g  = midx * MT;
    const int n0g  = nidx * NTN;
    const int kbase = kq * KQ;
    const int tile  = midx * 8 + nidx;
    const int feedA = midx * 8 + 2 * kq;
    const int feedB = feedA + 1;

    // ---- W slice into smem (once), fp16 hi/lo ----
    {
#pragma unroll
        for (int i = 0; i < 16; i++) {
            int u = tid + i * 512;
            int term = u >> 12;
            int v = u & 4095;
            int ch = v >> 9;
            int w2 = v & 511;
            int r = w2 >> 2, c = w2 & 3;
            const __half* src = (term ? g_w_lo : g_w_hi)
                + (size_t)(n0g + r) * H_SZ + kbase + ch * 32 + c * 8;
            uint32_t dst = sw + term * 65536 + ch * 8192 + r * 64
                         + ((c ^ ((r >> 1) & 3)) << 4);
            cp16(dst, src);
        }
        CP_COMMIT(); CP_WAIT_G0();
        __syncthreads();
    }

    // ldmatrix lane geometry (warp tile 16M x 32N)
    const int rA = wm * 16 + (lane & 15);
    const int cAadd = lane >> 4;
    const int swzA = (rA >> 1) & 3;
    const int rowB0 = wn * 32 + ((lane >> 4) << 3) + (lane & 7);
    const int rowB1 = rowB0 + 16;
    const int cBadd = (lane >> 3) & 1;
    const int swzB = (rowB0 >> 1) & 3;

    // reduce-thread geometry + invariants
    const int rloc = tid >> 5;               // 0..15
    const int c0   = lane * 4;               // 0..124
    const int pr   = kq * 16 + rloc;
    const int gr   = m0g + pr;
    const float4 bv = *reinterpret_cast<const float4*>(bias + n0g + c0);

    // issue one 8KB h quarter (64 K-cols, single fp16): 512 units, 1/thread
    auto issue_quarter = [&](const __half* h_in, int q) {
        int u = tid;
        int r = u >> 3;                  // 0..63
        int c = u & 7;                   // 0..7 (16B units in 128B row)
        int sub = c >> 2;                // 0..1 (32-col halves)
        int c4 = c & 3;
        const __half* src = h_in + (size_t)(m0g + r) * H_SZ
                          + kbase + q * 64 + sub * 32 + c4 * 8;
        uint32_t dst = sh + q * 8192 + sub * 4096
                     + r * 64 + ((c4 ^ ((r >> 1) & 3)) << 4);
        cp16(dst, src);
        CP_COMMIT();
    };

    float acc[4][4];

    // compute one quarter q (64 K-cols): 4 kk2 x (5 LDSM + 8 MMA)
    auto compute_quarter = [&](int q) {
#pragma unroll
        for (int kk2 = 0; kk2 < 4; kk2++) {
            const int sin = kk2 >> 1, kkin = kk2 & 1;
            const uint32_t hst = sh + q * 8192 + sin * 4096;
            const uint32_t wst = sw + (q * 2 + sin) * 8192;
            const int cA = ((kkin * 2 + cAadd) ^ swzA) << 4;
            const int cB = ((kkin * 2 + cBadd) ^ swzB) << 4;
            uint32_t a[4], bhi[8], blo[8];
            ldmx4(a, hst + rA * 64 + cA);
            ldmx4(bhi,     wst + rowB0 * 64 + cB);
            ldmx4(bhi + 4, wst + rowB1 * 64 + cB);
            ldmx4(blo,     wst + 65536 + rowB0 * 64 + cB);
            ldmx4(blo + 4, wst + 65536 + rowB1 * 64 + cB);
#pragma unroll
            for (int j = 0; j < 4; j++) {
                const uint32_t* b = &bhi[(j >> 1) * 4 + (j & 1) * 2];
                mma16816h(acc[j], a, b[0], b[1]);
            }
#pragma unroll
            for (int j = 0; j < 4; j++) {
                const uint32_t* b = &blo[(j >> 1) * 4 + (j & 1) * 2];
                mma16816h(acc[j], a, b[0], b[1]);
            }
        }
    };

    for (int t = 0; t < S_SZ; t++) {
        const __half* h_in  = g_h[t & 1];
        __half*       h_out = g_h[(t + 1) & 1];
        float* part = g_part[t & 1];

        // table L2 prefetch FIRST — tokens independent of h, overlaps feed wait
        if (tid < 16) {
            int grp = m0g + kq * 16 + tid;
            int tok = x[(size_t)grp * S_SZ + t];
            const char* p = (const char*)(g_table + (size_t)tok * H_SZ + n0g);
            l2pf(p); l2pf(p + 128); l2pf(p + 256); l2pf(p + 384);
        }

        // ---- per-warp feed wait ----
        if (t > 0 && lane == 0) {
            const int tgt = 4 * t;
            while (ld_acq(&g_done[feedA * 32]) < tgt) __nanosleep(32);
            while (ld_acq(&g_done[feedB * 32]) < tgt) __nanosleep(32);
        }
        __syncwarp();

        issue_quarter(h_in, 0);
        issue_quarter(h_in, 1);
        issue_quarter(h_in, 2);
        issue_quarter(h_in, 3);

#pragma unroll
        for (int j = 0; j < 4; j++)
#pragma unroll
            for (int q = 0; q < 4; q++) acc[j][q] = 0.f;

        CP_WAIT_G3(); __syncthreads(); compute_quarter(0);
        CP_WAIT_G2(); __syncthreads(); compute_quarter(1);
        CP_WAIT_G1(); __syncthreads(); compute_quarter(2);
        CP_WAIT_G0(); __syncthreads(); compute_quarter(3);

        // ---- hoisted epilogue operands ----
        const int tok = x[(size_t)gr * S_SZ + t];
        const float4 tv = *reinterpret_cast<const float4*>(
            g_table + (size_t)tok * H_SZ + n0g + c0);

        // ---- publish partials: own reduce strip (wm==kq) stays in SMEM ----
        if (wm == kq) {
            const int lr = lane >> 2;
#pragma unroll
            for (int j = 0; j < 4; j++) {
                const int c = wn * 32 + j * 8 + 2 * (lane & 3);
                *reinterpret_cast<float2*>(stg + lr * NTN + c) =
                    make_float2(acc[j][0], acc[j][1]);
                *reinterpret_cast<float2*>(stg + (lr + 8) * NTN + c) =
                    make_float2(acc[j][2], acc[j][3]);
            }
        } else {
            float* pb = part + ((size_t)tile * 4 + kq) * (MT * NTN);
            const int r = wm * 16 + (lane >> 2);
#pragma unroll
            for (int j = 0; j < 4; j++) {
                const int c = wn * 32 + j * 8 + 2 * (lane & 3);
                *reinterpret_cast<float2*>(pb + r * NTN + c) =
                    make_float2(acc[j][0], acc[j][1]);
                *reinterpret_cast<float2*>(pb + (r + 8) * NTN + c) =
                    make_float2(acc[j][2], acc[j][3]);
            }
        }
        __syncthreads();
        if (tid == 0) red_rel(&g_cnt[tile * 32]);
        if (lane == 0) {
            const int tgt = 4 * (t + 1);
            while (ld_acq(&g_cnt[tile * 32]) < tgt) __nanosleep(32);
        }
        __syncwarp();

        // ---- reduce my 16-row quarter + epilogue ----
        {
            const float* pb = part + (size_t)tile * 4 * (MT * NTN)
                            + pr * NTN + c0;
            float4 s = make_float4(0.f, 0.f, 0.f, 0.f);
#pragma unroll
            for (int q = 0; q < 4; q++) {              // fixed order: deterministic
                float4 a = (q == kq)
                    ? *reinterpret_cast<const float4*>(stg + rloc * NTN + c0)
                    : *reinterpret_cast<const float4*>(pb + q * (MT * NTN));
                s.x += a.x; s.y += a.y; s.z += a.z; s.w += a.w;
            }
            float v0 = tanhf(s.x + tv.x + bv.x);
            float v1 = tanhf(s.y + tv.y + bv.y);
            float v2 = tanhf(s.z + tv.z + bv.z);
            float v3 = tanhf(s.w + tv.w + bv.w);
            __half h4[4];
            h4[0] = __float2half(v0); h4[1] = __float2half(v1);
            h4[2] = __float2half(v2); h4[3] = __float2half(v3);
            const size_t ob = (size_t)gr * H_SZ + n0g + c0;
            *reinterpret_cast<uint2*>(h_out + ob) = *reinterpret_cast<uint2*>(h4);
            if (t == S_SZ - 1) {            // full-precision h_last for the MLP
                __nv_bfloat16 bh[4], bl[4];
                bh[0] = __float2bfloat16(v0); bl[0] = __float2bfloat16(v0 - __bfloat162float(bh[0]));
                bh[1] = __float2bfloat16(v1); bl[1] = __float2bfloat16(v1 - __bfloat162float(bh[1]));
                bh[2] = __float2bfloat16(v2); bl[2] = __float2bfloat16(v2 - __bfloat162float(bh[2]));
                bh[3] = __float2bfloat16(v3); bl[3] = __float2bfloat16(v3 - __bfloat162float(bh[3]));
                *reinterpret_cast<uint2*>(g_hl_hi + ob) = *reinterpret_cast<uint2*>(bh);
                *reinterpret_cast<uint2*>(g_hl_lo + ob) = *reinterpret_cast<uint2*>(bl);
            }
        }
        __syncthreads();
        if (tid == 0) red_rel(&g_done[tile * 32]);
    }
}

// ---------------- bf16-split GEMM (table precompute + MLP L1) ----------------
template<int MODE>
__global__ void __launch_bounds__(256) gemm_bf16s(
    const __nv_bfloat16* __restrict__ ahi_p, const __nv_bfloat16* __restrict__ alo_p,
    const __nv_bfloat16* __restrict__ bhi_p, const __nv_bfloat16* __restrict__ blo_p,
    int lda, int ldb, float* __restrict__ C, int ldc, int M, int NCH,
    const float* __restrict__ bias)
{
    extern __shared__ __align__(128) char smem[];
    const uint32_t sb = smem_u32(smem);
    const int tid  = threadIdx.x;
    const int lane = tid & 31;
    const int wid  = tid >> 5;
    const int wm   = wid >> 1;
    const int wn   = wid & 1;
    const int n0   = blockIdx.x * 64;
    const int m0   = blockIdx.y * 128;

    auto issue_tab = [&](uint32_t sbase, int ch) {
#pragma unroll
        for (int i = 0; i < 6; i++) {
            int u = tid + i * 256;
            if (u < 1024) {
                int term = u >> 9;
                int v = u & 511;
                int r = v >> 2, c = v & 3;
                int gm = m0 + r; if (gm >= M) gm = M - 1;
                const __nv_bfloat16* src = (term ? alo_p : ahi_p)
                    + (size_t)gm * lda + ch * 32 + c * 8;
                uint32_t dst = sbase + term * 8192 + r * 64
                             + ((c ^ ((r >> 1) & 3)) << 4);
                cp16(dst, src);
            } else {
                int v = u - 1024;
                int term = v >> 8;
                v &= 255;
                int r = v >> 2, c = v & 3;
                const __nv_bfloat16* src = (term ? blo_p : bhi_p)
                    + (size_t)(n0 + r) * ldb + ch * 32 + c * 8;
                uint32_t dst = sbase + 16384 + term * 4096 + r * 64
                             + ((c ^ ((r >> 1) & 3)) << 4);
                cp16(dst, src);
            }
        }
        CP_COMMIT();
    };

    issue_tab(sb + 0 * TB_STG, 0);
    issue_tab(sb + 1 * TB_STG, 1);
    issue_tab(sb + 2 * TB_STG, 2);

    const int rA0 = wm * 32 + (lane & 15);
    const int rA1 = rA0 + 16;
    const int cAadd = lane >> 4;
    const int swzA = (rA0 >> 1) & 3;
    const int rowB0 = wn * 32 + ((lane >> 4) << 3) + (lane & 7);
    const int rowB1 = rowB0 + 16;
    const int cBadd = (lane >> 3) & 1;
    const int swzB = (rowB0 >> 1) & 3;

    float acc[2][4][4];
#pragma unroll
    for (int i = 0; i < 2; i++)
#pragma unroll
        for (int j = 0; j < 4; j++)
#pragma unroll
            for (int q = 0; q < 4; q++) acc[i][j][q] = 0.f;

    for (int ch = 0; ch < NCH; ch++) {
        CP_WAIT_G2();
        __syncthreads();
        const uint32_t st = sb + (ch % 3) * TB_STG;
#pragma unroll
        for (int kk = 0; kk < 2; kk++) {
            const int cA = ((kk * 2 + cAadd) ^ swzA) << 4;
            const int cB = ((kk * 2 + cBadd) ^ swzB) << 4;
            uint32_t ahi[8], alo[8], bhi[8], blo[8];
            ldmx4(ahi,     st + rA0 * 64 + cA);
            ldmx4(ahi + 4, st + rA1 * 64 + cA);
            ldmx4(alo,     st + 8192 + rA0 * 64 + cA);
            ldmx4(alo + 4, st + 8192 + rA1 * 64 + cA);
            ldmx4(bhi,     st + 16384 + rowB0 * 64 + cB);
            ldmx4(bhi + 4, st + 16384 + rowB1 * 64 + cB);
            ldmx4(blo,     st + 20480 + rowB0 * 64 + cB);
            ldmx4(blo + 4, st + 20480 + rowB1 * 64 + cB);
#pragma unroll
            for (int i = 0; i < 2; i++)
#pragma unroll
                for (int j = 0; j < 4; j++) {
                    const uint32_t* b = &bhi[(j >> 1) * 4 + (j & 1) * 2];
                    mma16816bf(acc[i][j], ahi + i * 4, b[0], b[1]);
                }
#pragma unroll
            for (int i = 0; i < 2; i++)
#pragma unroll
                for (int j = 0; j < 4; j++) {
                    const uint32_t* b = &blo[(j >> 1) * 4 + (j & 1) * 2];
                    mma16816bf(acc[i][j], ahi + i * 4, b[0], b[1]);
                }
#pragma unroll
            for (int i = 0; i < 2; i++)
#pragma unroll
                for (int j = 0; j < 4; j++) {
                    const uint32_t* b = &bhi[(j >> 1) * 4 + (j & 1) * 2];
                    mma16816bf(acc[i][j], alo + i * 4, b[0], b[1]);
                }
        }
        __syncthreads();
        if (ch + 3 < NCH) issue_tab(sb + (ch % 3) * TB_STG, ch + 3);
        else CP_COMMIT();
    }

#pragma unroll
    for (int i = 0; i < 2; i++) {
        const int r = wm * 32 + i * 16 + (lane >> 2);
#pragma unroll
        for (int j = 0; j < 4; j++) {
            const int c = wn * 32 + j * 8 + 2 * (lane & 3);
            int gm = m0 + r;
            float2 v0 = make_float2(acc[i][j][0], acc[i][j][1]);
            float2 v1 = make_float2(acc[i][j][2], acc[i][j][3]);
            if (MODE == 1) {
                v0.x = fmaxf(v0.x + bias[n0 + c], 0.f);
                v0.y = fmaxf(v0.y + bias[n0 + c + 1], 0.f);
                v1.x = fmaxf(v1.x + bias[n0 + c], 0.f);
                v1.y = fmaxf(v1.y + bias[n0 + c + 1], 0.f);
            }
            if (gm < M)
                *reinterpret_cast<float2*>(C + (size_t)gm * ldc + n0 + c) = v0;
            if (gm + 8 < M)
                *reinterpret_cast<float2*>(C + (size_t)(gm + 8) * ldc + n0 + c) = v1;
        }
    }
}

// ---------------- prep / misc ----------------
__global__ void split_w_kernel(const float* __restrict__ W_ih,
                               __half* __restrict__ whi,
                               __half* __restrict__ wlo)
{
    int i = blockIdx.x * 256 + threadIdx.x;
    int j = i >> 10, k = i & (H_SZ - 1);
    float w = W_ih[(size_t)j * (E_SZ + H_SZ) + E_SZ + k];
    __half hi = __float2half(w);
    whi[i] = hi;
    wlo[i] = __float2half(w - __half2float(hi));
}

__global__ void split_e_kernel(const float* __restrict__ embed_W)
{
    size_t id = (size_t)blockIdx.x * 256 + threadIdx.x;
    int row = (int)(id / KP);
    int col = (int)(id - (size_t)row * KP);
    float v = (col < E_SZ) ? embed_W[(size_t)row * E_SZ + col] : 0.f;
    __nv_bfloat16 hi = __float2bfloat16(v);
    g_e_hi[id] = hi;
    g_e_lo[id] = __float2bfloat16(v - __bfloat162float(hi));
}

__global__ void split_we_kernel(const float* __restrict__ W_ih)
{
    int id = blockIdx.x * 256 + threadIdx.x;
    int row = id / KP;
    int col = id - row * KP;
    float v = (col < E_SZ) ? W_ih[(size_t)row * (E_SZ + H_SZ) + col] : 0.f;
    __nv_bfloat16 hi = __float2bfloat16(v);
    g_we_hi[id] = hi;
    g_we_lo[id] = __float2bfloat16(v - __bfloat162float(hi));
}

__global__ void split_w1_kernel(const float* __restrict__ W1)
{
    int i = blockIdx.x * 256 + threadIdx.x;
    float w = W1[i];
    __nv_bfloat16 hi = __float2bfloat16(w);
    g_w1_hi[i] = hi;
    g_w1_lo[i] = __float2bfloat16(w - __bfloat162float(hi));
}

__global__ void init_kernel(__half* h0, int* cnt, int* done) {
    int i = blockIdx.x * 256 + threadIdx.x;
    h0[i] = __float2half(0.f);
    if (i < 32 * 32) { cnt[i] = 0; done[i] = 0; }
}

__global__ void head2_kernel(const float* __restrict__ hid,
                             const float* __restrict__ W2,
                             const float* __restrict__ b2,
                             float* __restrict__ out)
{
    __shared__ float red[256];
    int b = blockIdx.x;
    float s = 0.f;
    for (int i = threadIdx.x; i < 2 * H_SZ; i += 256)
        s += hid[(size_t)b * 2 * H_SZ + i] * W2[i];
    red[threadIdx.x] = s;
    __syncthreads();
    for (int off = 128; off > 0; off >>= 1) {
        if (threadIdx.x < off) red[threadIdx.x] += red[threadIdx.x + off];
        __syncthreads();
    }
    if (threadIdx.x == 0) out[b] = red[0] + b2[0];
}

// ---------------- host ----------------
extern "C" void kernel_launch(void* const* d_in, const int* in_sizes, int n_in,
                              void* d_out, int out_size)
{
    const int*   x       = (const int*)  d_in[0];
    const float* embed_W = (const float*)d_in[1];
    const float* W_ih    = (const float*)d_in[2];
    const float* b_ih    = (const float*)d_in[3];
    const float* W1      = (const float*)d_in[4];
    const float* b1      = (const float*)d_in[5];
    const float* W2      = (const float*)d_in[6];
    const float* b2      = (const float*)d_in[7];
    float*       out     = (float*)d_out;

    float *table, *hid;
    int *cnt, *done;
    __half *h0p, *whi, *wlo;
    __nv_bfloat16 *hlhi, *hllo, *ehi, *elo, *wehi, *welo, *w1hi, *w1lo;
    cudaGetSymbolAddress((void**)&table, g_table);
    cudaGetSymbolAddress((void**)&hid,   g_hid);
    cudaGetSymbolAddress((void**)&cnt,   g_cnt);
    cudaGetSymbolAddress((void**)&done,  g_done);
    {
        void* p;
        cudaGetSymbolAddress(&p, g_h);     h0p  = (__half*)p;
        cudaGetSymbolAddress(&p, g_w_hi);  whi  = (__half*)p;
        cudaGetSymbolAddress(&p, g_w_lo);  wlo  = (__half*)p;
        cudaGetSymbolAddress(&p, g_hl_hi); hlhi = (__nv_bfloat16*)p;
        cudaGetSymbolAddress(&p, g_hl_lo); hllo = (__nv_bfloat16*)p;
        cudaGetSymbolAddress(&p, g_e_hi);  ehi  = (__nv_bfloat16*)p;
        cudaGetSymbolAddress(&p, g_e_lo);  elo  = (__nv_bfloat16*)p;
        cudaGetSymbolAddress(&p, g_we_hi); wehi = (__nv_bfloat16*)p;
        cudaGetSymbolAddress(&p, g_we_lo); welo = (__nv_bfloat16*)p;
        cudaGetSymbolAddress(&p, g_w1_hi); w1hi = (__nv_bfloat16*)p;
        cudaGetSymbolAddress(&p, g_w1_lo); w1lo = (__nv_bfloat16*)p;
    }

    static bool attr_done = false;
    if (!attr_done) {
        cudaFuncSetAttribute(rnn_kernel,
            cudaFuncAttributeMaxDynamicSharedMemorySize, SMEM_RNN);
        cudaFuncSetAttribute(gemm_bf16s<0>,
            cudaFuncAttributeMaxDynamicSharedMemorySize, SMEM_TAB);
        cudaFuncSetAttribute(gemm_bf16s<1>,
            cudaFuncAttributeMaxDynamicSharedMemorySize, SMEM_TAB);
        attr_done = true;
    }

    init_kernel<<<(B_SZ * H_SZ) / 256, 256>>>(h0p, cnt, done);
    split_w_kernel<<<(H_SZ * H_SZ) / 256, 256>>>(W_ih, whi, wlo);
    split_e_kernel<<<(int)(((size_t)V_SZ * KP) / 256), 256>>>(embed_W);
    split_we_kernel<<<(H_SZ * KP) / 256, 256>>>(W_ih);
    split_w1_kernel<<<(2 * H_SZ * H_SZ) / 256, 256>>>(W1);

    // vocab table on tensor cores (bf16-split, fp32-accurate)
    gemm_bf16s<0><<<dim3(H_SZ / 64, (V_SZ + 127) / 128), 256, SMEM_TAB>>>(
        ehi, elo, wehi, welo, KP, KP, table, H_SZ, V_SZ, KP / 32, nullptr);

    // all 512 recurrence steps in ONE persistent kernel (fp16 math)
    rnn_kernel<<<NCTA, 512, SMEM_RNN>>>(x, b_ih);

    // MLP L1 on tensor cores from bf16-split h_last
    gemm_bf16s<1><<<dim3(2 * H_SZ / 64, B_SZ / 128), 256, SMEM_TAB>>>(
        hlhi, hllo, w1hi, w1lo, H_SZ, H_SZ, hid, 2 * H_SZ, B_SZ, H_SZ / 32, b1);

    head2_kernel<<<B_SZ, 256>>>(hid, W2, b2, out);
}